// round 9
// baseline (speedup 1.0000x reference)
#include <cuda_runtime.h>
#include <cuda_bf16.h>
#include <math.h>
#include <cstdint>

#define B_  2
#define S_  2048
#define D_  2048
#define H_  16
#define KV_ 4
#define HD_ 128
#define NQKV 3072   // 2048 q + 512 k + 512 v

// ---------------------------------------------------------------------------
// Helpers (base-target instructions only: ldmatrix / mma.sync / cp.async)
// ---------------------------------------------------------------------------
__device__ __forceinline__ uint32_t smem_to_u32(const void* smem_ptr) {
    uint32_t addr;
    asm("{ .reg .u64 tmp; cvta.to.shared.u64 tmp, %1; cvt.u32.u64 %0, tmp; }"
        : "=r"(addr) : "l"(smem_ptr));
    return addr;
}
__device__ __forceinline__ void cp_async16(uint32_t s, const void* g) {
    asm volatile("cp.async.cg.shared.global [%0], [%1], 16;" :: "r"(s), "l"(g));
}
__device__ __forceinline__ void ldsm4(uint32_t* r, uint32_t addr) {
    asm volatile("ldmatrix.sync.aligned.m8n8.x4.shared.b16 {%0,%1,%2,%3}, [%4];"
        : "=r"(r[0]), "=r"(r[1]), "=r"(r[2]), "=r"(r[3]) : "r"(addr));
}
__device__ __forceinline__ void ldsm4t(uint32_t* r, uint32_t addr) {
    asm volatile("ldmatrix.sync.aligned.m8n8.x4.trans.shared.b16 {%0,%1,%2,%3}, [%4];"
        : "=r"(r[0]), "=r"(r[1]), "=r"(r[2]), "=r"(r[3]) : "r"(addr));
}
__device__ __forceinline__ void mma16816(float* d, const uint32_t* a, const uint32_t* b) {
    asm volatile(
        "mma.sync.aligned.m16n8k16.row.col.f32.bf16.bf16.f32 "
        "{%0,%1,%2,%3}, {%4,%5,%6,%7}, {%8,%9}, {%0,%1,%2,%3};"
        : "+f"(d[0]), "+f"(d[1]), "+f"(d[2]), "+f"(d[3])
        : "r"(a[0]), "r"(a[1]), "r"(a[2]), "r"(a[3]), "r"(b[0]), "r"(b[1]));
}
__device__ __forceinline__ uint32_t pack_bf16x2(float lo, float hi) {
    uint32_t r;
    asm("cvt.rn.bf16x2.f32 %0, %1, %2;" : "=r"(r) : "f"(hi), "f"(lo));
    return r;
}
__device__ __forceinline__ float ex2f(float x) {
    float r; asm("ex2.approx.f32 %0, %1;" : "=f"(r) : "f"(x)); return r;
}

// ---------------------------------------------------------------------------
// Scratch (allocation-free rule: device globals)
// ---------------------------------------------------------------------------
__device__ float g_q[B_*H_*S_*HD_];     // fp32 pre-RoPE
__device__ float g_k[B_*KV_*S_*HD_];    // fp32 pre-RoPE

__device__ __nv_bfloat16 g_xh[B_*S_*D_], g_xl[B_*S_*D_];
__device__ __nv_bfloat16 g_wqkvt_h[NQKV*D_], g_wqkvt_l[NQKV*D_];   // [3072,2048]
__device__ __nv_bfloat16 g_wot_h[D_*D_],  g_wot_l[D_*D_];
__device__ __nv_bfloat16 g_ah[B_*S_*H_*HD_], g_al[B_*S_*H_*HD_];

__device__ __nv_bfloat16 g_qh[B_*H_*S_*HD_],  g_ql[B_*H_*S_*HD_];
__device__ __nv_bfloat16 g_kh[B_*KV_*S_*HD_], g_kl[B_*KV_*S_*HD_];
__device__ __nv_bfloat16 g_vh[B_*KV_*S_*HD_], g_vl[B_*KV_*S_*HD_];

__device__ float2 g_rope[S_ * (HD_/2)];

// ---------------------------------------------------------------------------
// Elementwise fp32 -> (hi, lo) bf16 split.
// ---------------------------------------------------------------------------
__global__ __launch_bounds__(256) void split_kernel(
    const float4* __restrict__ in, __nv_bfloat162* __restrict__ oh,
    __nv_bfloat162* __restrict__ ol, int n4)
{
    int i = blockIdx.x * blockDim.x + threadIdx.x;
    if (i >= n4) return;
    float4 v = in[i];
    float vs[4] = {v.x, v.y, v.z, v.w};
    __nv_bfloat16 hh[4], ll[4];
    #pragma unroll
    for (int j = 0; j < 4; j++) {
        hh[j] = __float2bfloat16(vs[j]);
        ll[j] = __float2bfloat16(vs[j] - __bfloat162float(hh[j]));
    }
    oh[2*i]   = __halves2bfloat162(hh[0], hh[1]);
    oh[2*i+1] = __halves2bfloat162(hh[2], hh[3]);
    ol[2*i]   = __halves2bfloat162(ll[0], ll[1]);
    ol[2*i+1] = __halves2bfloat162(ll[2], ll[3]);
}

// ---------------------------------------------------------------------------
// ALL weight transposes in ONE launch (z selects region).
// ---------------------------------------------------------------------------
__global__ void transpose_all_kernel(
    const float* __restrict__ wq, const float* __restrict__ wk,
    const float* __restrict__ wv, const float* __restrict__ wo,
    __nv_bfloat16* __restrict__ qkv_h, __nv_bfloat16* __restrict__ qkv_l,
    __nv_bfloat16* __restrict__ wo_h,  __nv_bfloat16* __restrict__ wo_l)
{
    const int z = blockIdx.z;
    const float* in;
    __nv_bfloat16 *oh, *ol;
    int N;
    if (z == 0)      { in = wq; oh = qkv_h;                     ol = qkv_l;                     N = 2048; }
    else if (z == 1) { in = wk; oh = qkv_h + (size_t)2048 * D_; ol = qkv_l + (size_t)2048 * D_; N = 512; }
    else if (z == 2) { in = wv; oh = qkv_h + (size_t)2560 * D_; ol = qkv_l + (size_t)2560 * D_; N = 512; }
    else             { in = wo; oh = wo_h;                      ol = wo_l;                      N = 2048; }
    if (blockIdx.x * 32 >= N) return;

    __shared__ float tile[32][33];
    int tx = threadIdx.x, ty = threadIdx.y;
    int n0 = blockIdx.x * 32, k0 = blockIdx.y * 32;
    #pragma unroll
    for (int j = 0; j < 32; j += 8)
        tile[ty + j][tx] = in[(size_t)(k0 + ty + j) * N + n0 + tx];
    __syncthreads();
    #pragma unroll
    for (int j = 0; j < 32; j += 8) {
        float v = tile[tx][ty + j];
        __nv_bfloat16 h = __float2bfloat16(v);
        __nv_bfloat16 l = __float2bfloat16(v - __bfloat162float(h));
        size_t o = (size_t)(n0 + ty + j) * D_ + k0 + tx;
        oh[o] = h;
        ol[o] = l;
    }
}

// ---------------------------------------------------------------------------
// RoPE table: fp64 phase + two-term 2pi range reduction + HW sincosf.
// ---------------------------------------------------------------------------
__global__ __launch_bounds__(256) void rope_table_kernel()
{
    int idx = blockIdx.x * blockDim.x + threadIdx.x;
    if (idx >= S_ * (HD_/2)) return;
    int i = idx & 63, pos = idx >> 6;
    const double LOG2_THETA = 18.93156856932417108;   // log2(500000)
    double inv = exp2(-((double)i / 64.0) * LOG2_THETA);
    double f = (double)pos * inv;
    const double TWO_PI_HI = 6.283185307179586;
    const double TWO_PI_LO = 2.4492935982947064e-16;
    double n = rint(f * 0.15915494309189535);
    double r = f - n * TWO_PI_HI;
    r = r - n * TWO_PI_LO;
    float rc, rs;
    __sincosf((float)r, &rs, &rc);
    g_rope[idx] = make_float2(rc, rs);
}

// ---------------------------------------------------------------------------
// GEMM mainloop: 128x128 CTA tile, 256 threads, BK=32, double-buffered
// cp.async, 3-product split bf16, software-pipelined operand LDSMs.
// Product order: P1 = Ah*Bh, P2 = Ah*Bl (rolling bfl), P3 = Al*Bh.
// ---------------------------------------------------------------------------
#define PITCH 40
#define TILE_B (128 * PITCH * 2)
#define OFF_AH 0
#define OFF_AL (1 * TILE_B)
#define OFF_BH (2 * TILE_B)
#define OFF_BL (3 * TILE_B)
#define STAGE_B (4 * TILE_B)
#define MM_SMEM_BYTES (2 * STAGE_B)

__device__ __forceinline__ void gemm_mainloop(
    const __nv_bfloat16* __restrict__ Ah, const __nv_bfloat16* __restrict__ Al,
    const __nv_bfloat16* __restrict__ Bh, const __nv_bfloat16* __restrict__ Bl,
    int K, int row0, int col0, uint32_t su, int tid, float acc[2][8][4])
{
    const int wid = tid >> 5, lane = tid & 31;
    const int warp_m = wid & 3, warp_n = wid >> 2;

    const int nchunks = K >> 5;

    auto prefetch = [&](int ck, int stage) {
        const int k0 = ck << 5;
        const uint32_t sb = su + stage * STAGE_B;
        #pragma unroll
        for (int h = 0; h < 2; h++) {
            int c = tid + h * 256;
            int r = c >> 2, kc = c & 3;
            uint32_t so = (uint32_t)(r * PITCH * 2 + kc * 16);
            size_t ga = (size_t)(row0 + r) * K + k0 + kc * 8;
            size_t gb = (size_t)(col0 + r) * K + k0 + kc * 8;
            cp_async16(sb + OFF_AH + so, Ah + ga);
            cp_async16(sb + OFF_AL + so, Al + ga);
            cp_async16(sb + OFF_BH + so, Bh + gb);
            cp_async16(sb + OFF_BL + so, Bl + gb);
        }
        asm volatile("cp.async.commit_group;");
    };

    const int r8 = lane & 7, grp = lane >> 3;
    const int a_r = (grp & 1) * 8 + r8;
    const int a_c = (grp >> 1) * 8;
    const int b_r = (grp >> 1) * 8 + r8;
    const int b_c = (grp & 1) * 8;

    prefetch(0, 0);
    for (int ck = 0; ck < nchunks; ck++) {
        if (ck + 1 < nchunks) {
            prefetch(ck + 1, (ck + 1) & 1);
            asm volatile("cp.async.wait_group 1;");
        } else {
            asm volatile("cp.async.wait_group 0;");
        }
        __syncthreads();

        const uint32_t sb = su + (ck & 1) * STAGE_B;
        #pragma unroll
        for (int ks = 0; ks < 2; ks++) {
            const int klo = ks * 16;
            uint32_t afh[2][4], afl[2][4], bfh[4][4], bfl[4][4];
            uint32_t a_base = sb + ((warp_m * 32 + a_r) * PITCH + klo + a_c) * 2;
            uint32_t b_base = sb + ((warp_n * 64 + b_r) * PITCH + klo + b_c) * 2;
            const uint32_t MT_STRIDE = 16 * PITCH * 2;

            // upfront: afh + bfh
            #pragma unroll
            for (int mt = 0; mt < 2; mt++)
                ldsm4(afh[mt], a_base + OFF_AH + mt * MT_STRIDE);
            #pragma unroll
            for (int np = 0; np < 4; np++)
                ldsm4(bfh[np], b_base + OFF_BH + np * MT_STRIDE);

            // P1: Ah*Bh, inject bfl[0] load after np==2
            #pragma unroll
            for (int np = 0; np < 4; np++) {
                #pragma unroll
                for (int mt = 0; mt < 2; mt++) {
                    mma16816(acc[mt][2*np],   afh[mt], bfh[np]);
                    mma16816(acc[mt][2*np+1], afh[mt], bfh[np] + 2);
                }
                if (np == 2) ldsm4(bfl[0], b_base + OFF_BL);
            }

            // P2: Ah*Bl rolling (bfl[np+1] loaded one group ahead);
            //      afl loaded during the last group
            ldsm4(bfl[1], b_base + OFF_BL + 1 * MT_STRIDE);
            #pragma unroll
            for (int np = 0; np < 4; np++) {
                if (np == 0) ldsm4(bfl[2], b_base + OFF_BL + 2 * MT_STRIDE);
                if (np == 1) ldsm4(bfl[3], b_base + OFF_BL + 3 * MT_STRIDE);
                if (np == 2) {
                    ldsm4(afl[0], a_base + OFF_AL);
                    ldsm4(afl[1], a_base + OFF_AL + MT_STRIDE);
                }
                #pragma unroll
                for (int mt = 0; mt < 2; mt++) {
                    mma16816(acc[mt][2*np],   afh[mt], bfl[np]);
                    mma16816(acc[mt][2*np+1], afh[mt], bfl[np] + 2);
                }
            }

            // P3: Al*Bh (all operands resident)
            #pragma unroll
            for (int np = 0; np < 4; np++)
                #pragma unroll
                for (int mt = 0; mt < 2; mt++) {
                    mma16816(acc[mt][2*np],   afl[mt], bfh[np]);
                    mma16816(acc[mt][2*np+1], afl[mt], bfh[np] + 2);
                }
        }
        __syncthreads();
    }
}

// ---------------------------------------------------------------------------
// Merged QKV projection GEMM (V hi/lo split fused into epilogue).
// ---------------------------------------------------------------------------
__global__ __launch_bounds__(256, 2) void hmma_qkv_kernel(
    const __nv_bfloat16* __restrict__ Ah, const __nv_bfloat16* __restrict__ Al,
    const __nv_bfloat16* __restrict__ Bh, const __nv_bfloat16* __restrict__ Bl)
{
    extern __shared__ char smem[];
    const uint32_t su = smem_to_u32(smem);
    const int tid = threadIdx.x;
    const int wid = tid >> 5, lane = tid & 31;
    const int warp_m = wid & 3, warp_n = wid >> 2;
    const int row0 = blockIdx.y * 128, col0 = blockIdx.x * 128;

    float acc[2][8][4];
    #pragma unroll
    for (int i = 0; i < 2; i++)
        #pragma unroll
        for (int j = 0; j < 8; j++)
            #pragma unroll
            for (int k = 0; k < 4; k++) acc[i][j][k] = 0.0f;

    gemm_mainloop(Ah, Al, Bh, Bl, D_, row0, col0, su, tid, acc);

    const int r4 = lane >> 2, c2 = (lane & 3) * 2;
    const int region = (col0 < 2048) ? 0 : (col0 < 2560 ? 1 : 2);
    #pragma unroll
    for (int mt = 0; mt < 2; mt++) {
        #pragma unroll
        for (int half = 0; half < 2; half++) {
            int m = row0 + warp_m * 32 + mt * 16 + half * 8 + r4;
            int bb = m >> 11;
            int s  = m & (S_ - 1);
            #pragma unroll
            for (int nt = 0; nt < 8; nt++) {
                int n = col0 + warp_n * 64 + nt * 8 + c2;
                float vx = acc[mt][nt][half * 2 + 0];
                float vy = acc[mt][nt][half * 2 + 1];
                if (region == 0) {
                    int hh = n >> 7, d = n & 127;
                    float2 v = {vx, vy};
                    *(float2*)&g_q[(((size_t)bb * H_ + hh) * S_ + s) * HD_ + d] = v;
                } else if (region == 1) {
                    int nn = n - 2048;
                    int hh = nn >> 7, d = nn & 127;
                    float2 v = {vx, vy};
                    *(float2*)&g_k[(((size_t)bb * KV_ + hh) * S_ + s) * HD_ + d] = v;
                } else {
                    int nn = n - 2560;
                    int hh = nn >> 7, d = nn & 127;
                    size_t o = (((size_t)bb * KV_ + hh) * S_ + s) * HD_ + d;
                    float h0 = __bfloat162float(__float2bfloat16(vx));
                    float h1 = __bfloat162float(__float2bfloat16(vy));
                    *(uint32_t*)&g_vh[o] = pack_bf16x2(h0, h1);
                    *(uint32_t*)&g_vl[o] = pack_bf16x2(vx - h0, vy - h1);
                }
            }
        }
    }
}

// ---------------------------------------------------------------------------
// Output projection GEMM: plain row-major fp32 store into d_out.
// ---------------------------------------------------------------------------
__global__ __launch_bounds__(256, 2) void hmma_oproj_kernel(
    const __nv_bfloat16* __restrict__ Ah, const __nv_bfloat16* __restrict__ Al,
    const __nv_bfloat16* __restrict__ Bh, const __nv_bfloat16* __restrict__ Bl,
    float* __restrict__ C)
{
    extern __shared__ char smem[];
    const uint32_t su = smem_to_u32(smem);
    const int tid = threadIdx.x;
    const int wid = tid >> 5, lane = tid & 31;
    const int warp_m = wid & 3, warp_n = wid >> 2;
    const int row0 = blockIdx.y * 128, col0 = blockIdx.x * 128;

    float acc[2][8][4];
    #pragma unroll
    for (int i = 0; i < 2; i++)
        #pragma unroll
        for (int j = 0; j < 8; j++)
            #pragma unroll
            for (int k = 0; k < 4; k++) acc[i][j][k] = 0.0f;

    gemm_mainloop(Ah, Al, Bh, Bl, D_, row0, col0, su, tid, acc);

    const int r4 = lane >> 2, c2 = (lane & 3) * 2;
    #pragma unroll
    for (int mt = 0; mt < 2; mt++) {
        #pragma unroll
        for (int half = 0; half < 2; half++) {
            int m = row0 + warp_m * 32 + mt * 16 + half * 8 + r4;
            #pragma unroll
            for (int nt = 0; nt < 8; nt++) {
                int n = col0 + warp_n * 64 + nt * 8 + c2;
                float2 v;
                v.x = acc[mt][nt][half * 2 + 0];
                v.y = acc[mt][nt][half * 2 + 1];
                *(float2*)&C[(size_t)m * D_ + n] = v;
            }
        }
    }
}

// ---------------------------------------------------------------------------
// RoPE + split Q,K (table lookup).
// ---------------------------------------------------------------------------
__global__ __launch_bounds__(256) void rope_split_kernel(const int* __restrict__ pos_ids)
{
    const int NQP = B_ * H_  * S_ * (HD_ / 2);
    const int NKP = B_ * KV_ * S_ * (HD_ / 2);
    int idx = blockIdx.x * blockDim.x + threadIdx.x;
    const float* src;
    __nv_bfloat16 *dh, *dl;
    int nh;
    if (idx < NQP) { src = g_q; dh = g_qh; dl = g_ql; nh = H_; }
    else if (idx < NQP + NKP) { src = g_k; dh = g_kh; dl = g_kl; nh = KV_; idx -= NQP; }
    else return;

    int i  = idx & 63;
    int s  = (idx >> 6) & (S_ - 1);
    int bh = idx >> 17;
    int b  = bh / nh;
    int pos = pos_ids[b * S_ + s];

    float2 cs = g_rope[pos * 64 + i];
    float c = cs.x, sn = cs.y;

    size_t base = ((size_t)bh * S_ + s) * HD_;
    float v0 = src[base + i];
    float v1 = src[base + i + 64];
    float o0 = v0 * c - v1 * sn;
    float o1 = v1 * c + v0 * sn;
    __nv_bfloat16 h0 = __float2bfloat16(o0);
    __nv_bfloat16 h1 = __float2bfloat16(o1);
    dh[base + i]      = h0;
    dh[base + i + 64] = h1;
    dl[base + i]      = __float2bfloat16(o0 - __bfloat162float(h0));
    dl[base + i + 64] = __float2bfloat16(o1 - __bfloat162float(h1));
}

// ---------------------------------------------------------------------------
// HMMA flash attention. K/V in separate commit groups; software-pipelined
// operand LDSMs in both QK and PV phases.
// ---------------------------------------------------------------------------
#define FP 136
#define FT_B 17408
#define F_QH 0
#define F_QL (1 * FT_B)
#define F_KH (2 * FT_B)
#define F_KL (3 * FT_B)
#define F_VH (4 * FT_B)
#define F_VL (5 * FT_B)
#define FA_SMEM_BYTES (6 * FT_B)

__global__ __launch_bounds__(128, 2) void flash_hmma_kernel()
{
    extern __shared__ char smem[];
    const uint32_t su = smem_to_u32(smem);
    const int tid = threadIdx.x;
    const int wid = tid >> 5, lane = tid & 31;
    const int wrow = wid * 16;

    const int qt = gridDim.x - 1 - blockIdx.x;
    const int q0 = qt * 64;
    const int bh = blockIdx.y;
    const int b = bh >> 4, h = bh & 15;
    const int kvh = h >> 2;

    const __nv_bfloat16* Qhg = g_qh + (((size_t)b * H_  + h)   * S_ + q0) * HD_;
    const __nv_bfloat16* Qlg = g_ql + (((size_t)b * H_  + h)   * S_ + q0) * HD_;
    const __nv_bfloat16* Khg = g_kh + (((size_t)b * KV_ + kvh) * S_) * HD_;
    const __nv_bfloat16* Klg = g_kl + (((size_t)b * KV_ + kvh) * S_) * HD_;
    const __nv_bfloat16* Vhg = g_vh + (((size_t)b * KV_ + kvh) * S_) * HD_;
    const __nv_bfloat16* Vlg = g_vl + (((size_t)b * KV_ + kvh) * S_) * HD_;

    const int r8 = lane & 7, grp = lane >> 3;
    const int a_r = (grp & 1) * 8 + r8;
    const int a_c = (grp >> 1) * 8;
    const int b_r = (grp >> 1) * 8 + r8;
    const int b_c = (grp & 1) * 8;
    const int v_r = (grp & 1) * 8 + r8;
    const int v_c = (grp >> 1) * 8;

    #pragma unroll
    for (int it = 0; it < 8; it++) {
        int chunk = it * 128 + tid;
        int r = chunk >> 4, c = (chunk & 15) * 8;
        uint32_t so = (uint32_t)(r * FP + c) * 2;
        const size_t go = (size_t)r * HD_ + c;
        cp_async16(su + F_QH + so, Qhg + go);
        cp_async16(su + F_QL + so, Qlg + go);
    }
    asm volatile("cp.async.commit_group;");

    float out[16][4];
    #pragma unroll
    for (int i = 0; i < 16; i++)
        #pragma unroll
        for (int j = 0; j < 4; j++) out[i][j] = 0.0f;
    float m0 = -1e30f, m1 = -1e30f, l0 = 0.0f, l1 = 0.0f;

    const float cexp = 0.08838834764831845f * 1.4426950408889634f;
    const int ktiles = qt + 1;

    for (int kt = 0; kt < ktiles; kt++) {
        const int j0 = kt * 64;
        __syncthreads();
        #pragma unroll
        for (int it = 0; it < 8; it++) {
            int chunk = it * 128 + tid;
            int r = chunk >> 4, c = (chunk & 15) * 8;
            uint32_t so = (uint32_t)(r * FP + c) * 2;
            const size_t go = (size_t)(j0 + r) * HD_ + c;
            cp_async16(su + F_KH + so, Khg + go);
            cp_async16(su + F_KL + so, Klg + go);
        }
        asm volatile("cp.async.commit_group;");
        #pragma unroll
        for (int it = 0; it < 8; it++) {
            int chunk = it * 128 + tid;
            int r = chunk >> 4, c = (chunk & 15) * 8;
            uint32_t so = (uint32_t)(r * FP + c) * 2;
            const size_t go = (size_t)(j0 + r) * HD_ + c;
            cp_async16(su + F_VH + so, Vhg + go);
            cp_async16(su + F_VL + so, Vlg + go);
        }
        asm volatile("cp.async.commit_group;");
        asm volatile("cp.async.wait_group 1;");
        __syncthreads();

        // ---- S = Q @ K^T: P1 qh*kh, P2 qh*kl (rolling), P3 ql*kh ----
        float s[8][4];
        #pragma unroll
        for (int i = 0; i < 8; i++)
            #pragma unroll
            for (int j = 0; j < 4; j++) s[i][j] = 0.0f;

        #pragma unroll
        for (int ks = 0; ks < 8; ks++) {
            const int klo = ks * 16;
            uint32_t qh[4], ql[4], kfh[4][4], kfl[4][4];
            uint32_t qa = (uint32_t)((wrow + a_r) * FP + klo + a_c) * 2;
            uint32_t kb = (uint32_t)((b_r) * FP + klo + b_c) * 2;
            const uint32_t NG_STRIDE = 16 * FP * 2;

            ldsm4(qh, su + F_QH + qa);
            ldsm4(ql, su + F_QL + qa);
            #pragma unroll
            for (int ng = 0; ng < 4; ng++)
                ldsm4(kfh[ng], su + F_KH + kb + ng * NG_STRIDE);

            // P1: qh * kh, inject kfl[0..1]
            #pragma unroll
            for (int ng = 0; ng < 4; ng++) {
                mma16816(s[2*ng],   qh, kfh[ng]);
                mma16816(s[2*ng+1], qh, kfh[ng] + 2);
                if (ng == 1) ldsm4(kfl[0], su + F_KL + kb);
                if (ng == 2) ldsm4(kfl[1], su + F_KL + kb + 1 * NG_STRIDE);
            }
            // P2: qh * kl rolling
            #pragma unroll
            for (int ng = 0; ng < 4; ng++) {
                if (ng == 0) ldsm4(kfl[2], su + F_KL + kb + 2 * NG_STRIDE);
                if (ng == 1) ldsm4(kfl[3], su + F_KL + kb + 3 * NG_STRIDE);
                mma16816(s[2*ng],   qh, kfl[ng]);
                mma16816(s[2*ng+1], qh, kfl[ng] + 2);
            }
            // P3: ql * kh
            #pragma unroll
            for (int ng = 0; ng < 4; ng++) {
                mma16816(s[2*ng],   ql, kfh[ng]);
                mma16816(s[2*ng+1], ql, kfh[ng] + 2);
            }
        }

        // ---- causal mask (diagonal tile only) ----
        if (kt == ktiles - 1) {
            const int rl0 = wrow + (lane >> 2);
            const int cl  = 2 * (lane & 3);
            #pragma unroll
            for (int nt = 0; nt < 8; nt++) {
                int c0 = nt * 8 + cl;
                if (c0 > rl0)     s[nt][0] = -1e30f;
                if (c0 + 1 > rl0) s[nt][1] = -1e30f;
                if (c0 > rl0 + 8)     s[nt][2] = -1e30f;
                if (c0 + 1 > rl0 + 8) s[nt][3] = -1e30f;
            }
        }

        // ---- online softmax ----
        float rmax0 = -1e30f, rmax1 = -1e30f;
        #pragma unroll
        for (int nt = 0; nt < 8; nt++) {
            rmax0 = fmaxf(rmax0, fmaxf(s[nt][0], s[nt][1]));
            rmax1 = fmaxf(rmax1, fmaxf(s[nt][2], s[nt][3]));
        }
        #pragma unroll
        for (int o = 1; o <= 2; o <<= 1) {
            rmax0 = fmaxf(rmax0, __shfl_xor_sync(0xffffffffu, rmax0, o));
            rmax1 = fmaxf(rmax1, __shfl_xor_sync(0xffffffffu, rmax1, o));
        }
        float mn0 = fmaxf(m0, rmax0), mn1 = fmaxf(m1, rmax1);
        float alpha0 = ex2f((m0 - mn0) * cexp);
        float alpha1 = ex2f((m1 - mn1) * cexp);
        m0 = mn0; m1 = mn1;

        float rs0 = 0.0f, rs1 = 0.0f;
        #pragma unroll
        for (int nt = 0; nt < 8; nt++) {
            s[nt][0] = ex2f((s[nt][0] - mn0) * cexp);
            s[nt][1] = ex2f((s[nt][1] - mn0) * cexp);
            s[nt][2] = ex2f((s[nt][2] - mn1) * cexp);
            s[nt][3] = ex2f((s[nt][3] - mn1) * cexp);
            rs0 += s[nt][0] + s[nt][1];
            rs1 += s[nt][2] + s[nt][3];
        }
        #pragma unroll
        for (int o = 1; o <= 2; o <<= 1) {
            rs0 += __shfl_xor_sync(0xffffffffu, rs0, o);
            rs1 += __shfl_xor_sync(0xffffffffu, rs1, o);
        }
        l0 = l0 * alpha0 + rs0;
        l1 = l1 * alpha1 + rs1;
        #pragma unroll
        for (int nt = 0; nt < 16; nt++) {
            out[nt][0] *= alpha0; out[nt][1] *= alpha0;
            out[nt][2] *= alpha1; out[nt][3] *= alpha1;
        }

        // ---- wait V, then O += P @ V ----
        asm volatile("cp.async.wait_group 0;");
        __syncthreads();

        #pragma unroll
        for (int kk = 0; kk < 4; kk++) {
            uint32_t ph[4], pl[4];
            #pragma unroll
            for (int half = 0; half < 2; half++) {
                const float* sp = s[2*kk + half];
                #pragma unroll
                for (int rr = 0; rr < 2; rr++) {
                    float p0 = sp[rr*2], p1 = sp[rr*2+1];
                    float h0 = __bfloat162float(__float2bfloat16(p0));
                    float h1 = __bfloat162float(__float2bfloat16(p1));
                    ph[half*2 + rr] = pack_bf16x2(h0, h1);
                    pl[half*2 + rr] = pack_bf16x2(p0 - h0, p1 - h1);
                }
            }
            uint32_t vfh[8][4], vfl[8][4];
            uint32_t vb = (uint32_t)((kk * 16 + v_r) * FP + v_c) * 2;
            const uint32_t VN_STRIDE = 16 * 2;
            #pragma unroll
            for (int ng = 0; ng < 8; ng++)
                ldsm4t(vfh[ng], su + F_VH + vb + ng * VN_STRIDE);
            // P1: ph * vh, inject vfl[0..1]
            #pragma unroll
            for (int ng = 0; ng < 8; ng++) {
                mma16816(out[2*ng],   ph, vfh[ng]);
                mma16816(out[2*ng+1], ph, vfh[ng] + 2);
                if (ng == 4) ldsm4t(vfl[0], su + F_VL + vb);
                if (ng == 6) ldsm4t(vfl[1], su + F_VL + vb + 1 * VN_STRIDE);
            }
            // P2: ph * vl rolling, 2 groups ahead
            #pragma unroll
            for (int ng = 0; ng < 8; ng++) {
                if (ng + 2 < 8) ldsm4t(vfl[ng + 2], su + F_VL + vb + (ng + 2) * VN_STRIDE);
                mma16816(out[2*ng],   ph, vfl[ng]);
                mma16816(out[2*ng+1], ph, vfl[ng] + 2);
            }
            // P3: pl * vh
            #pragma unroll
            for (int ng = 0; ng < 8; ng++) {
                mma16816(out[2*ng],   pl, vfh[ng]);
                mma16816(out[2*ng+1], pl, vfh[ng] + 2);
            }
        }
    }

    // ---- epilogue ----
    float il0 = 1.0f / l0, il1 = 1.0f / l1;
    const int row0g = q0 + wrow + (lane >> 2);
    const int cl = 2 * (lane & 3);
    #pragma unroll
    for (int ng = 0; ng < 16; ng++) {
        int col = h * HD_ + ng * 8 + cl;
        #pragma unroll
        for (int half = 0; half < 2; half++) {
            int rowg = row0g + half * 8;
            float v0 = out[ng][half*2]     * (half ? il1 : il0);
            float v1 = out[ng][half*2 + 1] * (half ? il1 : il0);
            float h0 = __bfloat162float(__float2bfloat16(v0));
            float h1 = __bfloat162float(__float2bfloat16(v1));
            size_t o = ((size_t)b * S_ + rowg) * (H_ * HD_) + col;
            *(uint32_t*)&g_ah[o] = pack_bf16x2(h0, h1);
            *(uint32_t*)&g_al[o] = pack_bf16x2(v0 - h0, v1 - h1);
        }
    }
}

// ---------------------------------------------------------------------------
// Launch. Keep hmma_qkv at capture slot (index 3).
// ---------------------------------------------------------------------------
extern "C" void kernel_launch(void* const* d_in, const int* in_sizes, int n_in,
                              void* d_out, int out_size)
{
    const float* x  = (const float*)d_in[0];
    const float* wq = (const float*)d_in[1];
    const float* wk = (const float*)d_in[2];
    const float* wv = (const float*)d_in[3];
    const float* wo = (const float*)d_in[4];
    const int* pos  = (const int*)d_in[6];

    __nv_bfloat16 *xh, *xl, *wqkvh, *wqkvl, *woth, *wotl, *ah, *al;
    cudaGetSymbolAddress((void**)&xh, g_xh);   cudaGetSymbolAddress((void**)&xl, g_xl);
    cudaGetSymbolAddress((void**)&wqkvh, g_wqkvt_h);
    cudaGetSymbolAddress((void**)&wqkvl, g_wqkvt_l);
    cudaGetSymbolAddress((void**)&woth, g_wot_h); cudaGetSymbolAddress((void**)&wotl, g_wot_l);
    cudaGetSymbolAddress((void**)&ah, g_ah);   cudaGetSymbolAddress((void**)&al, g_al);

    const int M = B_ * S_;
    dim3 blk256(256);

    // [0] split x -> bf16 hi/lo
    {
        int n4 = M * D_ / 4;
        split_kernel<<<(n4 + 255) / 256, blk256>>>((const float4*)x,
            (__nv_bfloat162*)xh, (__nv_bfloat162*)xl, n4);
    }
    // [1] all weight transposes in one launch
    transpose_all_kernel<<<dim3(64, 64, 4), dim3(32, 8)>>>(
        wq, wk, wv, wo, wqkvh, wqkvl, woth, wotl);

    // [2] RoPE cos/sin table
    rope_table_kernel<<<(S_ * (HD_/2) + 255) / 256, blk256>>>();

    cudaFuncSetAttribute(hmma_qkv_kernel, cudaFuncAttributeMaxDynamicSharedMemorySize, MM_SMEM_BYTES);
    cudaFuncSetAttribute(hmma_oproj_kernel, cudaFuncAttributeMaxDynamicSharedMemorySize, MM_SMEM_BYTES);

    // [3] merged QKV projection  <-- capture slot
    hmma_qkv_kernel<<<dim3(NQKV/128, M/128), blk256, MM_SMEM_BYTES>>>(
        xh, xl, wqkvh, wqkvl);

    // [4] RoPE + split Q,K -> bf16 hi/lo
    int npairs = B_ * H_ * S_ * (HD_ / 2) + B_ * KV_ * S_ * (HD_ / 2);
    rope_split_kernel<<<(npairs + 255) / 256, blk256>>>(pos);

    // [5] flash attention
    cudaFuncSetAttribute(flash_hmma_kernel, cudaFuncAttributeMaxDynamicSharedMemorySize, FA_SMEM_BYTES);
    flash_hmma_kernel<<<dim3(S_ / 64, B_ * H_), 128, FA_SMEM_BYTES>>>();

    // [6] output projection straight into d_out
    hmma_oproj_kernel<<<dim3(D_/128, M/128), blk256, MM_SMEM_BYTES>>>(
        ah, al, woth, wotl, (float*)d_out);
}

// round 10
// speedup vs baseline: 1.5061x; 1.5061x over previous
#include <cuda_runtime.h>
#include <cuda_bf16.h>
#include <cuda_fp16.h>
#include <math.h>
#include <cstdint>

#define B_  2
#define S_  2048
#define D_  2048
#define H_  16
#define KV_ 4
#define HD_ 128
#define NQKV 3072   // 2048 q + 512 k + 512 v

// ---------------------------------------------------------------------------
// Helpers (base-target instructions only: ldmatrix / mma.sync / cp.async)
// ---------------------------------------------------------------------------
__device__ __forceinline__ uint32_t smem_to_u32(const void* smem_ptr) {
    uint32_t addr;
    asm("{ .reg .u64 tmp; cvta.to.shared.u64 tmp, %1; cvt.u32.u64 %0, tmp; }"
        : "=r"(addr) : "l"(smem_ptr));
    return addr;
}
__device__ __forceinline__ void cp_async16(uint32_t s, const void* g) {
    asm volatile("cp.async.cg.shared.global [%0], [%1], 16;" :: "r"(s), "l"(g));
}
__device__ __forceinline__ void ldsm4(uint32_t* r, uint32_t addr) {
    asm volatile("ldmatrix.sync.aligned.m8n8.x4.shared.b16 {%0,%1,%2,%3}, [%4];"
        : "=r"(r[0]), "=r"(r[1]), "=r"(r[2]), "=r"(r[3]) : "r"(addr));
}
__device__ __forceinline__ void ldsm4t(uint32_t* r, uint32_t addr) {
    asm volatile("ldmatrix.sync.aligned.m8n8.x4.trans.shared.b16 {%0,%1,%2,%3}, [%4];"
        : "=r"(r[0]), "=r"(r[1]), "=r"(r[2]), "=r"(r[3]) : "r"(addr));
}
// fp16 MMA, fp32 accumulate
__device__ __forceinline__ void mma16816(float* d, const uint32_t* a, const uint32_t* b) {
    asm volatile(
        "mma.sync.aligned.m16n8k16.row.col.f32.f16.f16.f32 "
        "{%0,%1,%2,%3}, {%4,%5,%6,%7}, {%8,%9}, {%0,%1,%2,%3};"
        : "+f"(d[0]), "+f"(d[1]), "+f"(d[2]), "+f"(d[3])
        : "r"(a[0]), "r"(a[1]), "r"(a[2]), "r"(a[3]), "r"(b[0]), "r"(b[1]));
}
__device__ __forceinline__ uint32_t pack_h2(float lo, float hi) {
    __half2 t = __floats2half2_rn(lo, hi);
    return *(uint32_t*)&t;
}
__device__ __forceinline__ float ex2f(float x) {
    float r; asm("ex2.approx.f32 %0, %1;" : "=f"(r) : "f"(x)); return r;
}

// ---------------------------------------------------------------------------
// Scratch (allocation-free rule: device globals)
// ---------------------------------------------------------------------------
__device__ float g_q[B_*H_*S_*HD_];     // fp32 pre-RoPE
__device__ float g_k[B_*KV_*S_*HD_];    // fp32 pre-RoPE

__device__ __half g_xh[B_*S_*D_], g_xl[B_*S_*D_];        // x split (fp16 hi/lo)
__device__ __half g_wqkvt[NQKV*D_];                      // weights single fp16 [3072,2048]
__device__ __half g_wot[D_*D_];                          // wo single fp16 [N,K]
__device__ __half g_ah[B_*S_*H_*HD_], g_al[B_*S_*H_*HD_];// attn out split

__device__ __half g_qh[B_*H_*S_*HD_], g_ql[B_*H_*S_*HD_];// roped Q split
__device__ __half g_kf[B_*KV_*S_*HD_];                   // roped K single fp16
__device__ __half g_vf[B_*KV_*S_*HD_];                   // V single fp16

__device__ float2 g_rope[S_ * (HD_/2)];

// ---------------------------------------------------------------------------
// Elementwise fp32 -> (hi, lo) fp16 split.
// ---------------------------------------------------------------------------
__global__ __launch_bounds__(256) void split_kernel(
    const float4* __restrict__ in, __half2* __restrict__ oh,
    __half2* __restrict__ ol, int n4)
{
    int i = blockIdx.x * blockDim.x + threadIdx.x;
    if (i >= n4) return;
    float4 v = in[i];
    float vs[4] = {v.x, v.y, v.z, v.w};
    float hh[4];
    #pragma unroll
    for (int j = 0; j < 4; j++) hh[j] = __half2float(__float2half_rn(vs[j]));
    oh[2*i]   = __floats2half2_rn(hh[0], hh[1]);
    oh[2*i+1] = __floats2half2_rn(hh[2], hh[3]);
    ol[2*i]   = __floats2half2_rn(vs[0] - hh[0], vs[1] - hh[1]);
    ol[2*i+1] = __floats2half2_rn(vs[2] - hh[2], vs[3] - hh[3]);
}

// ---------------------------------------------------------------------------
// ALL weight transposes in ONE launch: fp32 [K,N] -> single fp16 [N,K].
// ---------------------------------------------------------------------------
__global__ void transpose_all_kernel(
    const float* __restrict__ wq, const float* __restrict__ wk,
    const float* __restrict__ wv, const float* __restrict__ wo,
    __half* __restrict__ qkv, __half* __restrict__ wot)
{
    const int z = blockIdx.z;
    const float* in;
    __half* oh;
    int N;
    if (z == 0)      { in = wq; oh = qkv;                     N = 2048; }
    else if (z == 1) { in = wk; oh = qkv + (size_t)2048 * D_; N = 512; }
    else if (z == 2) { in = wv; oh = qkv + (size_t)2560 * D_; N = 512; }
    else             { in = wo; oh = wot;                     N = 2048; }
    if (blockIdx.x * 32 >= N) return;

    __shared__ float tile[32][33];
    int tx = threadIdx.x, ty = threadIdx.y;
    int n0 = blockIdx.x * 32, k0 = blockIdx.y * 32;
    #pragma unroll
    for (int j = 0; j < 32; j += 8)
        tile[ty + j][tx] = in[(size_t)(k0 + ty + j) * N + n0 + tx];
    __syncthreads();
    #pragma unroll
    for (int j = 0; j < 32; j += 8) {
        float v = tile[tx][ty + j];
        oh[(size_t)(n0 + ty + j) * D_ + k0 + tx] = __float2half_rn(v);
    }
}

// ---------------------------------------------------------------------------
// RoPE table: fp64 phase + two-term 2pi range reduction + HW sincosf.
// ---------------------------------------------------------------------------
__global__ __launch_bounds__(256) void rope_table_kernel()
{
    int idx = blockIdx.x * blockDim.x + threadIdx.x;
    if (idx >= S_ * (HD_/2)) return;
    int i = idx & 63, pos = idx >> 6;
    const double LOG2_THETA = 18.93156856932417108;   // log2(500000)
    double inv = exp2(-((double)i / 64.0) * LOG2_THETA);
    double f = (double)pos * inv;
    const double TWO_PI_HI = 6.283185307179586;
    const double TWO_PI_LO = 2.4492935982947064e-16;
    double n = rint(f * 0.15915494309189535);
    double r = f - n * TWO_PI_HI;
    r = r - n * TWO_PI_LO;
    float rc, rs;
    __sincosf((float)r, &rs, &rc);
    g_rope[idx] = make_float2(rc, rs);
}

// ---------------------------------------------------------------------------
// GEMM mainloop: 128x128 CTA tile, 256 threads, BK=32, double-buffered
// cp.async. fp16 2-product: (Ah + Al) * Bf. B fragments reused in registers.
// ---------------------------------------------------------------------------
#define PITCH 40
#define TILE_B (128 * PITCH * 2)
#define OFF_AH 0
#define OFF_AL (1 * TILE_B)
#define OFF_BF (2 * TILE_B)
#define STAGE_B (3 * TILE_B)
#define MM_SMEM_BYTES (2 * STAGE_B)

__device__ __forceinline__ void gemm_mainloop(
    const __half* __restrict__ Ah, const __half* __restrict__ Al,
    const __half* __restrict__ Bf,
    int K, int row0, int col0, uint32_t su, int tid, float acc[2][8][4])
{
    const int wid = tid >> 5, lane = tid & 31;
    const int warp_m = wid & 3, warp_n = wid >> 2;

    const int nchunks = K >> 5;

    auto prefetch = [&](int ck, int stage) {
        const int k0 = ck << 5;
        const uint32_t sb = su + stage * STAGE_B;
        #pragma unroll
        for (int h = 0; h < 2; h++) {
            int c = tid + h * 256;
            int r = c >> 2, kc = c & 3;
            uint32_t so = (uint32_t)(r * PITCH * 2 + kc * 16);
            size_t ga = (size_t)(row0 + r) * K + k0 + kc * 8;
            size_t gb = (size_t)(col0 + r) * K + k0 + kc * 8;
            cp_async16(sb + OFF_AH + so, Ah + ga);
            cp_async16(sb + OFF_AL + so, Al + ga);
            cp_async16(sb + OFF_BF + so, Bf + gb);
        }
        asm volatile("cp.async.commit_group;");
    };

    const int r8 = lane & 7, grp = lane >> 3;
    const int a_r = (grp & 1) * 8 + r8;
    const int a_c = (grp >> 1) * 8;
    const int b_r = (grp >> 1) * 8 + r8;
    const int b_c = (grp & 1) * 8;

    prefetch(0, 0);
    for (int ck = 0; ck < nchunks; ck++) {
        if (ck + 1 < nchunks) {
            prefetch(ck + 1, (ck + 1) & 1);
            asm volatile("cp.async.wait_group 1;");
        } else {
            asm volatile("cp.async.wait_group 0;");
        }
        __syncthreads();

        const uint32_t sb = su + (ck & 1) * STAGE_B;
        #pragma unroll
        for (int ks = 0; ks < 2; ks++) {
            const int klo = ks * 16;
            uint32_t afh[2][4], afl[2][4], bf[4][4];
            #pragma unroll
            for (int mt = 0; mt < 2; mt++) {
                uint32_t ao = ((warp_m * 32 + mt * 16 + a_r) * PITCH + klo + a_c) * 2;
                ldsm4(afh[mt], sb + OFF_AH + ao);
                ldsm4(afl[mt], sb + OFF_AL + ao);
            }
            #pragma unroll
            for (int np = 0; np < 4; np++)
                ldsm4(bf[np], sb + OFF_BF +
                      ((warp_n * 64 + np * 16 + b_r) * PITCH + klo + b_c) * 2);
            // P1: Ah * Bf
            #pragma unroll
            for (int np = 0; np < 4; np++)
                #pragma unroll
                for (int mt = 0; mt < 2; mt++) {
                    mma16816(acc[mt][2*np],   afh[mt], bf[np]);
                    mma16816(acc[mt][2*np+1], afh[mt], bf[np] + 2);
                }
            // P2: Al * Bf (B reused from registers)
            #pragma unroll
            for (int np = 0; np < 4; np++)
                #pragma unroll
                for (int mt = 0; mt < 2; mt++) {
                    mma16816(acc[mt][2*np],   afl[mt], bf[np]);
                    mma16816(acc[mt][2*np+1], afl[mt], bf[np] + 2);
                }
        }
        __syncthreads();
    }
}

// ---------------------------------------------------------------------------
// Merged QKV projection GEMM (V fp16 rounding fused into epilogue).
// ---------------------------------------------------------------------------
__global__ __launch_bounds__(256, 2) void hmma_qkv_kernel(
    const __half* __restrict__ Ah, const __half* __restrict__ Al,
    const __half* __restrict__ Bf)
{
    extern __shared__ char smem[];
    const uint32_t su = smem_to_u32(smem);
    const int tid = threadIdx.x;
    const int wid = tid >> 5, lane = tid & 31;
    const int warp_m = wid & 3, warp_n = wid >> 2;
    const int row0 = blockIdx.y * 128, col0 = blockIdx.x * 128;

    float acc[2][8][4];
    #pragma unroll
    for (int i = 0; i < 2; i++)
        #pragma unroll
        for (int j = 0; j < 8; j++)
            #pragma unroll
            for (int k = 0; k < 4; k++) acc[i][j][k] = 0.0f;

    gemm_mainloop(Ah, Al, Bf, D_, row0, col0, su, tid, acc);

    const int r4 = lane >> 2, c2 = (lane & 3) * 2;
    const int region = (col0 < 2048) ? 0 : (col0 < 2560 ? 1 : 2);
    #pragma unroll
    for (int mt = 0; mt < 2; mt++) {
        #pragma unroll
        for (int half = 0; half < 2; half++) {
            int m = row0 + warp_m * 32 + mt * 16 + half * 8 + r4;
            int bb = m >> 11;
            int s  = m & (S_ - 1);
            #pragma unroll
            for (int nt = 0; nt < 8; nt++) {
                int n = col0 + warp_n * 64 + nt * 8 + c2;
                float vx = acc[mt][nt][half * 2 + 0];
                float vy = acc[mt][nt][half * 2 + 1];
                if (region == 0) {
                    int hh = n >> 7, d = n & 127;
                    float2 v = {vx, vy};
                    *(float2*)&g_q[(((size_t)bb * H_ + hh) * S_ + s) * HD_ + d] = v;
                } else if (region == 1) {
                    int nn = n - 2048;
                    int hh = nn >> 7, d = nn & 127;
                    float2 v = {vx, vy};
                    *(float2*)&g_k[(((size_t)bb * KV_ + hh) * S_ + s) * HD_ + d] = v;
                } else {
                    int nn = n - 2560;
                    int hh = nn >> 7, d = nn & 127;
                    size_t o = (((size_t)bb * KV_ + hh) * S_ + s) * HD_ + d;
                    *(__half2*)&g_vf[o] = __floats2half2_rn(vx, vy);
                }
            }
        }
    }
}

// ---------------------------------------------------------------------------
// Output projection GEMM: plain row-major fp32 store into d_out.
// ---------------------------------------------------------------------------
__global__ __launch_bounds__(256, 2) void hmma_oproj_kernel(
    const __half* __restrict__ Ah, const __half* __restrict__ Al,
    const __half* __restrict__ Bf, float* __restrict__ C)
{
    extern __shared__ char smem[];
    const uint32_t su = smem_to_u32(smem);
    const int tid = threadIdx.x;
    const int wid = tid >> 5, lane = tid & 31;
    const int warp_m = wid & 3, warp_n = wid >> 2;
    const int row0 = blockIdx.y * 128, col0 = blockIdx.x * 128;

    float acc[2][8][4];
    #pragma unroll
    for (int i = 0; i < 2; i++)
        #pragma unroll
        for (int j = 0; j < 8; j++)
            #pragma unroll
            for (int k = 0; k < 4; k++) acc[i][j][k] = 0.0f;

    gemm_mainloop(Ah, Al, Bf, D_, row0, col0, su, tid, acc);

    const int r4 = lane >> 2, c2 = (lane & 3) * 2;
    #pragma unroll
    for (int mt = 0; mt < 2; mt++) {
        #pragma unroll
        for (int half = 0; half < 2; half++) {
            int m = row0 + warp_m * 32 + mt * 16 + half * 8 + r4;
            #pragma unroll
            for (int nt = 0; nt < 8; nt++) {
                int n = col0 + warp_n * 64 + nt * 8 + c2;
                float2 v;
                v.x = acc[mt][nt][half * 2 + 0];
                v.y = acc[mt][nt][half * 2 + 1];
                *(float2*)&C[(size_t)m * D_ + n] = v;
            }
        }
    }
}

// ---------------------------------------------------------------------------
// RoPE + convert: Q -> fp16 hi/lo, K -> single fp16.
// ---------------------------------------------------------------------------
__global__ __launch_bounds__(256) void rope_split_kernel(const int* __restrict__ pos_ids)
{
    const int NQP = B_ * H_  * S_ * (HD_ / 2);
    const int NKP = B_ * KV_ * S_ * (HD_ / 2);
    int idx = blockIdx.x * blockDim.x + threadIdx.x;
    bool isQ;
    const float* src;
    int nh;
    if (idx < NQP) { src = g_q; nh = H_; isQ = true; }
    else if (idx < NQP + NKP) { src = g_k; nh = KV_; idx -= NQP; isQ = false; }
    else return;

    int i  = idx & 63;
    int s  = (idx >> 6) & (S_ - 1);
    int bh = idx >> 17;
    int b  = bh / nh;
    int pos = pos_ids[b * S_ + s];

    float2 cs = g_rope[pos * 64 + i];
    float c = cs.x, sn = cs.y;

    size_t base = ((size_t)bh * S_ + s) * HD_;
    float v0 = src[base + i];
    float v1 = src[base + i + 64];
    float o0 = v0 * c - v1 * sn;
    float o1 = v1 * c + v0 * sn;
    if (isQ) {
        float h0 = __half2float(__float2half_rn(o0));
        float h1 = __half2float(__float2half_rn(o1));
        g_qh[base + i]      = __float2half_rn(h0);
        g_qh[base + i + 64] = __float2half_rn(h1);
        g_ql[base + i]      = __float2half_rn(o0 - h0);
        g_ql[base + i + 64] = __float2half_rn(o1 - h1);
    } else {
        g_kf[base + i]      = __float2half_rn(o0);
        g_kf[base + i + 64] = __float2half_rn(o1);
    }
}

// ---------------------------------------------------------------------------
// HMMA flash attention, fp16: QK = (Qh+Ql)*K (2 products, K regs reused);
// PV = (Ph+Pl)*V (2 products, V regs reused). K/V separate commit groups.
// smem: QH, QL, KF, VF tiles (4 x 17408 B).
// ---------------------------------------------------------------------------
#define FP 136
#define FT_B 17408
#define F_QH 0
#define F_QL (1 * FT_B)
#define F_KF (2 * FT_B)
#define F_VF (3 * FT_B)
#define FA_SMEM_BYTES (4 * FT_B)

__global__ __launch_bounds__(128, 2) void flash_hmma_kernel()
{
    extern __shared__ char smem[];
    const uint32_t su = smem_to_u32(smem);
    const int tid = threadIdx.x;
    const int wid = tid >> 5, lane = tid & 31;
    const int wrow = wid * 16;

    const int qt = gridDim.x - 1 - blockIdx.x;
    const int q0 = qt * 64;
    const int bh = blockIdx.y;
    const int b = bh >> 4, h = bh & 15;
    const int kvh = h >> 2;

    const __half* Qhg = g_qh + (((size_t)b * H_  + h)   * S_ + q0) * HD_;
    const __half* Qlg = g_ql + (((size_t)b * H_  + h)   * S_ + q0) * HD_;
    const __half* Kfg = g_kf + (((size_t)b * KV_ + kvh) * S_) * HD_;
    const __half* Vfg = g_vf + (((size_t)b * KV_ + kvh) * S_) * HD_;

    const int r8 = lane & 7, grp = lane >> 3;
    const int a_r = (grp & 1) * 8 + r8;
    const int a_c = (grp >> 1) * 8;
    const int b_r = (grp >> 1) * 8 + r8;
    const int b_c = (grp & 1) * 8;
    const int v_r = (grp & 1) * 8 + r8;
    const int v_c = (grp >> 1) * 8;

    #pragma unroll
    for (int it = 0; it < 8; it++) {
        int chunk = it * 128 + tid;
        int r = chunk >> 4, c = (chunk & 15) * 8;
        uint32_t so = (uint32_t)(r * FP + c) * 2;
        const size_t go = (size_t)r * HD_ + c;
        cp_async16(su + F_QH + so, Qhg + go);
        cp_async16(su + F_QL + so, Qlg + go);
    }
    asm volatile("cp.async.commit_group;");

    float out[16][4];
    #pragma unroll
    for (int i = 0; i < 16; i++)
        #pragma unroll
        for (int j = 0; j < 4; j++) out[i][j] = 0.0f;
    float m0 = -1e30f, m1 = -1e30f, l0 = 0.0f, l1 = 0.0f;

    const float cexp = 0.08838834764831845f * 1.4426950408889634f;
    const int ktiles = qt + 1;

    for (int kt = 0; kt < ktiles; kt++) {
        const int j0 = kt * 64;
        __syncthreads();
        // K group
        #pragma unroll
        for (int it = 0; it < 8; it++) {
            int chunk = it * 128 + tid;
            int r = chunk >> 4, c = (chunk & 15) * 8;
            uint32_t so = (uint32_t)(r * FP + c) * 2;
            cp_async16(su + F_KF + so, Kfg + (size_t)(j0 + r) * HD_ + c);
        }
        asm volatile("cp.async.commit_group;");
        // V group (overlaps QK + softmax)
        #pragma unroll
        for (int it = 0; it < 8; it++) {
            int chunk = it * 128 + tid;
            int r = chunk >> 4, c = (chunk & 15) * 8;
            uint32_t so = (uint32_t)(r * FP + c) * 2;
            cp_async16(su + F_VF + so, Vfg + (size_t)(j0 + r) * HD_ + c);
        }
        asm volatile("cp.async.commit_group;");
        asm volatile("cp.async.wait_group 1;");
        __syncthreads();

        // ---- S = (Qh + Ql) @ K^T : 2 products, K regs reused ----
        float s[8][4];
        #pragma unroll
        for (int i = 0; i < 8; i++)
            #pragma unroll
            for (int j = 0; j < 4; j++) s[i][j] = 0.0f;

        #pragma unroll
        for (int ks = 0; ks < 8; ks++) {
            const int klo = ks * 16;
            uint32_t qh[4], ql[4], kf[4][4];
            uint32_t qa = (uint32_t)((wrow + a_r) * FP + klo + a_c) * 2;
            ldsm4(qh, su + F_QH + qa);
            ldsm4(ql, su + F_QL + qa);
            #pragma unroll
            for (int ng = 0; ng < 4; ng++)
                ldsm4(kf[ng], su + F_KF +
                      (uint32_t)((ng * 16 + b_r) * FP + klo + b_c) * 2);
            #pragma unroll
            for (int ng = 0; ng < 4; ng++) {
                mma16816(s[2*ng],   qh, kf[ng]);
                mma16816(s[2*ng+1], qh, kf[ng] + 2);
            }
            #pragma unroll
            for (int ng = 0; ng < 4; ng++) {
                mma16816(s[2*ng],   ql, kf[ng]);
                mma16816(s[2*ng+1], ql, kf[ng] + 2);
            }
        }

        // ---- causal mask (diagonal tile only) ----
        if (kt == ktiles - 1) {
            const int rl0 = wrow + (lane >> 2);
            const int cl  = 2 * (lane & 3);
            #pragma unroll
            for (int nt = 0; nt < 8; nt++) {
                int c0 = nt * 8 + cl;
                if (c0 > rl0)     s[nt][0] = -1e30f;
                if (c0 + 1 > rl0) s[nt][1] = -1e30f;
                if (c0 > rl0 + 8)     s[nt][2] = -1e30f;
                if (c0 + 1 > rl0 + 8) s[nt][3] = -1e30f;
            }
        }

        // ---- online softmax ----
        float rmax0 = -1e30f, rmax1 = -1e30f;
        #pragma unroll
        for (int nt = 0; nt < 8; nt++) {
            rmax0 = fmaxf(rmax0, fmaxf(s[nt][0], s[nt][1]));
            rmax1 = fmaxf(rmax1, fmaxf(s[nt][2], s[nt][3]));
        }
        #pragma unroll
        for (int o = 1; o <= 2; o <<= 1) {
            rmax0 = fmaxf(rmax0, __shfl_xor_sync(0xffffffffu, rmax0, o));
            rmax1 = fmaxf(rmax1, __shfl_xor_sync(0xffffffffu, rmax1, o));
        }
        float mn0 = fmaxf(m0, rmax0), mn1 = fmaxf(m1, rmax1);
        float alpha0 = ex2f((m0 - mn0) * cexp);
        float alpha1 = ex2f((m1 - mn1) * cexp);
        m0 = mn0; m1 = mn1;

        float rs0 = 0.0f, rs1 = 0.0f;
        #pragma unroll
        for (int nt = 0; nt < 8; nt++) {
            s[nt][0] = ex2f((s[nt][0] - mn0) * cexp);
            s[nt][1] = ex2f((s[nt][1] - mn0) * cexp);
            s[nt][2] = ex2f((s[nt][2] - mn1) * cexp);
            s[nt][3] = ex2f((s[nt][3] - mn1) * cexp);
            rs0 += s[nt][0] + s[nt][1];
            rs1 += s[nt][2] + s[nt][3];
        }
        #pragma unroll
        for (int o = 1; o <= 2; o <<= 1) {
            rs0 += __shfl_xor_sync(0xffffffffu, rs0, o);
            rs1 += __shfl_xor_sync(0xffffffffu, rs1, o);
        }
        l0 = l0 * alpha0 + rs0;
        l1 = l1 * alpha1 + rs1;
        #pragma unroll
        for (int nt = 0; nt < 16; nt++) {
            out[nt][0] *= alpha0; out[nt][1] *= alpha0;
            out[nt][2] *= alpha1; out[nt][3] *= alpha1;
        }

        // ---- wait V, then O += (Ph + Pl) @ V : 2 products, V regs reused ----
        asm volatile("cp.async.wait_group 0;");
        __syncthreads();

        #pragma unroll
        for (int kk = 0; kk < 4; kk++) {
            uint32_t ph[4], pl[4];
            #pragma unroll
            for (int half = 0; half < 2; half++) {
                const float* sp = s[2*kk + half];
                #pragma unroll
                for (int rr = 0; rr < 2; rr++) {
                    float p0 = sp[rr*2], p1 = sp[rr*2+1];
                    float h0 = __half2float(__float2half_rn(p0));
                    float h1 = __half2float(__float2half_rn(p1));
                    ph[half*2 + rr] = pack_h2(h0, h1);
                    pl[half*2 + rr] = pack_h2(p0 - h0, p1 - h1);
                }
            }
            uint32_t vf[8][4];
            uint32_t vb = (uint32_t)((kk * 16 + v_r) * FP + v_c) * 2;
            const uint32_t VN_STRIDE = 16 * 2;
            #pragma unroll
            for (int ng = 0; ng < 8; ng++)
                ldsm4t(vf[ng], su + F_VF + vb + ng * VN_STRIDE);
            #pragma unroll
            for (int ng = 0; ng < 8; ng++) {
                mma16816(out[2*ng],   ph, vf[ng]);
                mma16816(out[2*ng+1], ph, vf[ng] + 2);
            }
            #pragma unroll
            for (int ng = 0; ng < 8; ng++) {
                mma16816(out[2*ng],   pl, vf[ng]);
                mma16816(out[2*ng+1], pl, vf[ng] + 2);
            }
        }
    }

    // ---- epilogue: normalize, split fp16 hi/lo, write (B,S,H*HD) ----
    float il0 = 1.0f / l0, il1 = 1.0f / l1;
    const int row0g = q0 + wrow + (lane >> 2);
    const int cl = 2 * (lane & 3);
    #pragma unroll
    for (int ng = 0; ng < 16; ng++) {
        int col = h * HD_ + ng * 8 + cl;
        #pragma unroll
        for (int half = 0; half < 2; half++) {
            int rowg = row0g + half * 8;
            float v0 = out[ng][half*2]     * (half ? il1 : il0);
            float v1 = out[ng][half*2 + 1] * (half ? il1 : il0);
            float h0 = __half2float(__float2half_rn(v0));
            float h1 = __half2float(__float2half_rn(v1));
            size_t o = ((size_t)b * S_ + rowg) * (H_ * HD_) + col;
            *(__half2*)&g_ah[o] = __floats2half2_rn(h0, h1);
            *(__half2*)&g_al[o] = __floats2half2_rn(v0 - h0, v1 - h1);
        }
    }
}

// ---------------------------------------------------------------------------
// Launch. Keep hmma_qkv at capture slot (index 3).
// ---------------------------------------------------------------------------
extern "C" void kernel_launch(void* const* d_in, const int* in_sizes, int n_in,
                              void* d_out, int out_size)
{
    const float* x  = (const float*)d_in[0];
    const float* wq = (const float*)d_in[1];
    const float* wk = (const float*)d_in[2];
    const float* wv = (const float*)d_in[3];
    const float* wo = (const float*)d_in[4];
    const int* pos  = (const int*)d_in[6];

    __half *xh, *xl, *wqkv, *wot, *ah, *al;
    cudaGetSymbolAddress((void**)&xh, g_xh);   cudaGetSymbolAddress((void**)&xl, g_xl);
    cudaGetSymbolAddress((void**)&wqkv, g_wqkvt);
    cudaGetSymbolAddress((void**)&wot, g_wot);
    cudaGetSymbolAddress((void**)&ah, g_ah);   cudaGetSymbolAddress((void**)&al, g_al);

    const int M = B_ * S_;
    dim3 blk256(256);

    // [0] split x -> fp16 hi/lo
    {
        int n4 = M * D_ / 4;
        split_kernel<<<(n4 + 255) / 256, blk256>>>((const float4*)x,
            (__half2*)xh, (__half2*)xl, n4);
    }
    // [1] all weight transposes in one launch (single fp16)
    transpose_all_kernel<<<dim3(64, 64, 4), dim3(32, 8)>>>(
        wq, wk, wv, wo, wqkv, wot);

    // [2] RoPE cos/sin table
    rope_table_kernel<<<(S_ * (HD_/2) + 255) / 256, blk256>>>();

    cudaFuncSetAttribute(hmma_qkv_kernel, cudaFuncAttributeMaxDynamicSharedMemorySize, MM_SMEM_BYTES);
    cudaFuncSetAttribute(hmma_oproj_kernel, cudaFuncAttributeMaxDynamicSharedMemorySize, MM_SMEM_BYTES);

    // [3] merged QKV projection  <-- capture slot
    hmma_qkv_kernel<<<dim3(NQKV/128, M/128), blk256, MM_SMEM_BYTES>>>(xh, xl, wqkv);

    // [4] RoPE: Q -> fp16 hi/lo, K -> fp16
    int npairs = B_ * H_ * S_ * (HD_ / 2) + B_ * KV_ * S_ * (HD_ / 2);
    rope_split_kernel<<<(npairs + 255) / 256, blk256>>>(pos);

    // [5] flash attention
    cudaFuncSetAttribute(flash_hmma_kernel, cudaFuncAttributeMaxDynamicSharedMemorySize, FA_SMEM_BYTES);
    flash_hmma_kernel<<<dim3(S_ / 64, B_ * H_), 128, FA_SMEM_BYTES>>>();

    // [6] output projection straight into d_out
    hmma_oproj_kernel<<<dim3(D_/128, M/128), blk256, MM_SMEM_BYTES>>>(
        ah, al, wot, (float*)d_out);
}